// round 13
// baseline (speedup 1.0000x reference)
#include <cuda_runtime.h>
#include <cuda_bf16.h>
#include <stdint.h>
#include <cstdint>
#include <math.h>

#define BB 16
#define NN 8192
#define CC 128
#define NC (NN*CC)          // 1048576
#define BNC (BB*NC)         // 16777216

// ---------------- scratch (device globals; no dynamic allocation) ----------
__device__ __nv_bfloat16 g_cbf[4][BNC]; // centered bf16: 0 hf_s, 1 hf_p, 2 lf_s, 3 lf_p
__device__ float  g_G[2][BB][CC*CC];    // Gram partials  (2 MB)
__device__ float  g_n2[2][2][BB][CC];   // [pair][0=x/1=s][b][c] centered sum-of-squares
__device__ int    g_ord[2][NN];         // descending-stable argsort of gt_rank rows 0,1
__device__ int    g_cnt[2];             // count(gt_rank[b] > 0)
__device__ double g_acc[8];             // 0 pearson, 1 sep, 2 cost, 3 recon_hf, 4 recon_lf

// ---------------- helpers ---------------------------------------------------
__device__ __forceinline__ float wredf(float v) {
    #pragma unroll
    for (int o = 16; o; o >>= 1) v += __shfl_down_sync(0xffffffffu, v, o);
    return v;
}

__device__ __forceinline__ void block_add(double v, double* target) {
    __shared__ double sd[8];
    #pragma unroll
    for (int o = 16; o; o >>= 1) v += __shfl_down_sync(0xffffffffu, v, o);
    int lane = threadIdx.x & 31, w = threadIdx.x >> 5;
    if (lane == 0) sd[w] = v;
    __syncthreads();
    if (threadIdx.x == 0) {
        double s = 0;
        int nw = blockDim.x >> 5;
        for (int i = 0; i < nw; i++) s += sd[i];
        atomicAdd(target, s);
    }
}

// PTX wrappers
__device__ __forceinline__ void ldsm_x4_t(uint32_t& r0, uint32_t& r1,
                                          uint32_t& r2, uint32_t& r3, uint32_t addr) {
    asm volatile("ldmatrix.sync.aligned.m8n8.x4.trans.shared.b16 {%0,%1,%2,%3}, [%4];"
        : "=r"(r0), "=r"(r1), "=r"(r2), "=r"(r3) : "r"(addr));
}

__device__ __forceinline__ void mma_bf16_16816(float& c0, float& c1, float& c2, float& c3,
                                               uint32_t a0, uint32_t a1, uint32_t a2, uint32_t a3,
                                               uint32_t b0, uint32_t b1) {
    asm volatile(
        "mma.sync.aligned.m16n8k16.row.col.f32.bf16.bf16.f32 "
        "{%0,%1,%2,%3}, {%4,%5,%6,%7}, {%8,%9}, {%0,%1,%2,%3};"
        : "+f"(c0), "+f"(c1), "+f"(c2), "+f"(c3)
        : "r"(a0), "r"(a1), "r"(a2), "r"(a3), "r"(b0), "r"(b1));
}

__device__ __forceinline__ void cpa16(uint32_t dst, const void* src) {
    asm volatile("cp.async.cg.shared.global [%0], [%1], 16;" :: "r"(dst), "l"(src));
}
__device__ __forceinline__ void cpa_commit() {
    asm volatile("cp.async.commit_group;" ::: "memory");
}
template<int N>
__device__ __forceinline__ void cpa_wait() {
    asm volatile("cp.async.wait_group %0;" :: "n"(N) : "memory");
}

// ---------------- kernels ---------------------------------------------------

__global__ void k_init() {
    int i = blockIdx.x * 256 + threadIdx.x;
    if (i < 2*BB*CC*CC) ((float*)g_G)[i] = 0.f;
    else {
        int j = i - 2*BB*CC*CC;
        if (j < 2*2*BB*CC) ((float*)g_n2)[j] = 0.f;
    }
    if (i < 8) g_acc[i] = 0.0;
    if (i < 2) g_cnt[i] = 0;
}

// fused batch-mean + centering + bf16 conversion (one read of each tensor)
__global__ void k_prep(const float* __restrict__ a, const float* __restrict__ b,
                       const float* __restrict__ c, const float* __restrict__ d) {
    int which = blockIdx.y;
    const float4* src;
    switch (which) {
        case 0:  src = (const float4*)a; break;
        case 1:  src = (const float4*)b; break;
        case 2:  src = (const float4*)c; break;
        default: src = (const float4*)d; break;
    }
    uint2* dst = (uint2*)g_cbf[which];
    int idx = blockIdx.x * 256 + threadIdx.x;       // float4 index 0..NC/4-1

    float4 v[BB];
    #pragma unroll
    for (int bb = 0; bb < BB; bb++) v[bb] = src[(size_t)bb * (NC/4) + idx];

    float4 m = make_float4(0.f, 0.f, 0.f, 0.f);
    #pragma unroll
    for (int bb = 0; bb < BB; bb++) {
        m.x += v[bb].x; m.y += v[bb].y; m.z += v[bb].z; m.w += v[bb].w;
    }
    m.x *= 0.0625f; m.y *= 0.0625f; m.z *= 0.0625f; m.w *= 0.0625f;

    #pragma unroll
    for (int bb = 0; bb < BB; bb++) {
        __nv_bfloat162 lo = __floats2bfloat162_rn(v[bb].x - m.x, v[bb].y - m.y);
        __nv_bfloat162 hi = __floats2bfloat162_rn(v[bb].z - m.z, v[bb].w - m.w);
        dst[(size_t)bb * (NC/4) + idx] = make_uint2(*(uint32_t*)&lo, *(uint32_t*)&hi);
    }
}

// ---- fused kernel: CTAs [0,256) = bf16 tensor-core split-K Gram;
//      CTAs [256,296) = reconstruction MSE (overlaps DRAM with gemm's compute).
// gemm: 8 warps (2x4 grid, 64x32 warp tiles), cp.async 3-stage ring,
// SMEM tile [32 k-rows][128 cols] bf16, 16B-chunk XOR swizzle,
// n2 sums-of-squares derived from MMA fragments.
__device__ __forceinline__ uint32_t swz(int row, int cbyte) {
    return (uint32_t)(row * 256 + (cbyte ^ ((row & 7) << 4)));
}

#define STAGE_BYTES 16384   // X 8KB + S 8KB
#define GEMM_CTAS 256
#define RECON_CTAS_PER_PAIR 20

__global__ __launch_bounds__(256, 2)
void k_gemm(const float* __restrict__ r_hf, const float* __restrict__ hf,
            const float* __restrict__ r_lf, const float* __restrict__ lf) {
    __shared__ __align__(16) unsigned char smem[3 * STAGE_BYTES];   // 48KB ring

    int t = threadIdx.x;

    // ================= recon branch (CTA-granular) =================
    if (blockIdx.x >= GEMM_CTAS) {
        int rid  = blockIdx.x - GEMM_CTAS;              // 0..39
        int pair = rid & 1;
        int slice = rid >> 1;                            // 0..19
        const float4* r = (const float4*)(pair ? r_lf : r_hf);
        const float4* o = (const float4*)(pair ? lf   : hf);
        int base = slice * 256 + t;                      // 0..5119
        const int nthr = RECON_CTAS_PER_PAIR * 256;      // 5120
        float local = 0.f;
        for (int i = base; i < BNC/16; i += nthr) {      // 4 float4 groups
            #pragma unroll
            for (int u = 0; u < 4; u++) {
                float4 a = r[i * 4 + u], bq = o[i * 4 + u];
                float dx = a.x - bq.x, dy = a.y - bq.y;
                float dz = a.z - bq.z, dw = a.w - bq.w;
                local += dx*dx + dy*dy + dz*dz + dw*dw;
            }
        }
        block_add((double)local, &g_acc[3 + pair]);
        return;
    }

    // ================= gemm branch =================
    int cta  = blockIdx.x;
    int pair = cta >> 7;            // 0..1
    int b    = (cta >> 3) & 15;     // 0..15
    int kchunk = cta & 7;           // 0..7

    const __nv_bfloat16* Xb = g_cbf[pair ? 2 : 0] + (size_t)b * NC;
    const __nv_bfloat16* Sb = g_cbf[pair ? 3 : 1] + (size_t)b * NC;

    int lane = t & 31, warp = t >> 5;
    int wm = (warp >> 2) * 64;          // warp m-origin (c-dim of X): 0 or 64
    int wn = (warp & 3) * 32;           // warp n-origin (c-dim of S): 0..96

    uint32_t sbase = (uint32_t)__cvta_generic_to_shared(smem);

    // loader mapping: 256 threads x 32B per tensor per stage (2 x 16B chunks)
    int lrow = t >> 3;                  // 0..31
    int lc8  = t & 7;                   // chunk pair 0..7
    uint32_t ld0 = swz(lrow, lc8 * 32);
    uint32_t ld1 = swz(lrow, lc8 * 32 + 16);
    int lsrc = lrow * CC + lc8 * 16;    // bf16 element offset within stage

    // ldmatrix.x4.trans lane address pieces
    int a_r = ((lane >> 4) & 1) * 8 + (lane & 7);
    int a_c = ((lane >> 3) & 1) * 8;
    int b_r = ((lane >> 3) & 1) * 8 + (lane & 7);
    int b_c = ((lane >> 4) & 1) * 8;

    float acc[4][16];
    #pragma unroll
    for (int i = 0; i < 4; i++)
        #pragma unroll
        for (int j = 0; j < 16; j++) acc[i][j] = 0.f;

    float sqa[8] = {0.f,0.f,0.f,0.f,0.f,0.f,0.f,0.f}; // warps 0,4: X col sums (64 rows)
    float sqb[4] = {0.f,0.f,0.f,0.f};                  // warps 0..3: S col sums (32 rows)
    bool doA = ((warp & 3) == 0);
    bool doB = ((warp >> 2) == 0);

    int kbase = kchunk * 1024;          // 32 stages of 32 k-rows

    // prologue: issue stages 0..1
    #pragma unroll
    for (int st = 0; st < 2; st++) {
        uint32_t sb = sbase + st * STAGE_BYTES;
        int gsrc = (kbase + st * 32) * CC + lsrc;
        cpa16(sb + ld0,        Xb + gsrc);
        cpa16(sb + ld1,        Xb + gsrc + 8);
        cpa16(sb + 8192 + ld0, Sb + gsrc);
        cpa16(sb + 8192 + ld1, Sb + gsrc + 8);
        cpa_commit();
    }

    int slot = 0;   // ring slot of stage st
    for (int st = 0; st < 32; st++) {
        cpa_wait<1>();
        __syncthreads();

        // issue stage st+2 into the slot just freed
        int nslot = slot + 2; if (nslot >= 3) nslot -= 3;
        if (st + 2 < 32) {
            uint32_t sb = sbase + nslot * STAGE_BYTES;
            int gsrc = (kbase + (st + 2) * 32) * CC + lsrc;
            cpa16(sb + ld0,        Xb + gsrc);
            cpa16(sb + ld1,        Xb + gsrc + 8);
            cpa16(sb + 8192 + ld0, Sb + gsrc);
            cpa16(sb + 8192 + ld1, Sb + gsrc + 8);
        }
        cpa_commit();

        uint32_t sX = sbase + slot * STAGE_BYTES;
        uint32_t sS = sX + 8192;
        #pragma unroll
        for (int kk = 0; kk < 32; kk += 16) {
            uint32_t A0[4], A1[4], A2[4], A3[4], B0[4], B1[4];
            int ra = kk + a_r;
            ldsm_x4_t(A0[0], A0[1], A0[2], A0[3], sX + swz(ra, (wm      + a_c) * 2));
            ldsm_x4_t(A1[0], A1[1], A1[2], A1[3], sX + swz(ra, (wm + 16 + a_c) * 2));
            ldsm_x4_t(A2[0], A2[1], A2[2], A2[3], sX + swz(ra, (wm + 32 + a_c) * 2));
            ldsm_x4_t(A3[0], A3[1], A3[2], A3[3], sX + swz(ra, (wm + 48 + a_c) * 2));
            int rb = kk + b_r;
            ldsm_x4_t(B0[0], B0[1], B0[2], B0[3], sS + swz(rb, (wn      + b_c) * 2));
            ldsm_x4_t(B1[0], B1[1], B1[2], B1[3], sS + swz(rb, (wn + 16 + b_c) * 2));

            #pragma unroll
            for (int i = 0; i < 4; i++) {
                uint32_t* Ai = (i == 0) ? A0 : (i == 1) ? A1 : (i == 2) ? A2 : A3;
                mma_bf16_16816(acc[i][0],  acc[i][1],  acc[i][2],  acc[i][3],
                               Ai[0], Ai[1], Ai[2], Ai[3], B0[0], B0[1]);
                mma_bf16_16816(acc[i][4],  acc[i][5],  acc[i][6],  acc[i][7],
                               Ai[0], Ai[1], Ai[2], Ai[3], B0[2], B0[3]);
                mma_bf16_16816(acc[i][8],  acc[i][9],  acc[i][10], acc[i][11],
                               Ai[0], Ai[1], Ai[2], Ai[3], B1[0], B1[1]);
                mma_bf16_16816(acc[i][12], acc[i][13], acc[i][14], acc[i][15],
                               Ai[0], Ai[1], Ai[2], Ai[3], B1[2], B1[3]);
            }

            // fragment-derived sums of squares (each tile element counted once)
            if (doA) {
                #pragma unroll
                for (int i = 0; i < 4; i++) {
                    uint32_t* Ai = (i == 0) ? A0 : (i == 1) ? A1 : (i == 2) ? A2 : A3;
                    float2 f0 = __bfloat1622float2(*(__nv_bfloat162*)&Ai[0]);
                    float2 f1 = __bfloat1622float2(*(__nv_bfloat162*)&Ai[1]);
                    float2 f2 = __bfloat1622float2(*(__nv_bfloat162*)&Ai[2]);
                    float2 f3 = __bfloat1622float2(*(__nv_bfloat162*)&Ai[3]);
                    sqa[i*2+0] += f0.x*f0.x + f0.y*f0.y + f2.x*f2.x + f2.y*f2.y;
                    sqa[i*2+1] += f1.x*f1.x + f1.y*f1.y + f3.x*f3.x + f3.y*f3.y;
                }
            }
            if (doB) {
                float2 g0 = __bfloat1622float2(*(__nv_bfloat162*)&B0[0]);
                float2 g1 = __bfloat1622float2(*(__nv_bfloat162*)&B0[1]);
                float2 g2 = __bfloat1622float2(*(__nv_bfloat162*)&B0[2]);
                float2 g3 = __bfloat1622float2(*(__nv_bfloat162*)&B0[3]);
                float2 h0 = __bfloat1622float2(*(__nv_bfloat162*)&B1[0]);
                float2 h1 = __bfloat1622float2(*(__nv_bfloat162*)&B1[1]);
                float2 h2 = __bfloat1622float2(*(__nv_bfloat162*)&B1[2]);
                float2 h3 = __bfloat1622float2(*(__nv_bfloat162*)&B1[3]);
                sqb[0] += g0.x*g0.x + g0.y*g0.y + g1.x*g1.x + g1.y*g1.y;
                sqb[1] += g2.x*g2.x + g2.y*g2.y + g3.x*g3.x + g3.y*g3.y;
                sqb[2] += h0.x*h0.x + h0.y*h0.y + h1.x*h1.x + h1.y*h1.y;
                sqb[3] += h2.x*h2.x + h2.y*h2.y + h3.x*h3.x + h3.y*h3.y;
            }
        }
        __syncthreads();
        slot++; if (slot == 3) slot = 0;
    }

    // epilogue: merge split-K partials
    float* Gp = g_G[pair][b];
    int grp = lane >> 2, tg = lane & 3;
    #pragma unroll
    for (int i = 0; i < 4; i++) {
        #pragma unroll
        for (int j2 = 0; j2 < 4; j2++) {
            int m = wm + 16 * i + grp;
            int d = wn + 8 * j2 + tg * 2;
            atomicAdd(&Gp[m * CC + d],           acc[i][j2 * 4 + 0]);
            atomicAdd(&Gp[m * CC + d + 1],       acc[i][j2 * 4 + 1]);
            atomicAdd(&Gp[(m + 8) * CC + d],     acc[i][j2 * 4 + 2]);
            atomicAdd(&Gp[(m + 8) * CC + d + 1], acc[i][j2 * 4 + 3]);
        }
    }
    // n2 partials: xor-shuffle reduce over the 4 lanes sharing a column
    if (doA) {
        #pragma unroll
        for (int j = 0; j < 8; j++) {
            sqa[j] += __shfl_xor_sync(0xffffffffu, sqa[j], 1);
            sqa[j] += __shfl_xor_sync(0xffffffffu, sqa[j], 2);
        }
        if ((lane & 3) == 0) {
            #pragma unroll
            for (int j = 0; j < 8; j++) {
                int m = wm + 16 * (j >> 1) + 8 * (j & 1) + grp;
                atomicAdd(&g_n2[pair][0][b][m], sqa[j]);
            }
        }
    }
    if (doB) {
        #pragma unroll
        for (int j = 0; j < 4; j++) {
            sqb[j] += __shfl_xor_sync(0xffffffffu, sqb[j], 1);
            sqb[j] += __shfl_xor_sync(0xffffffffu, sqb[j], 2);
        }
        if ((lane & 3) == 0) {
            #pragma unroll
            for (int j = 0; j < 4; j++) {
                int n = wn + 8 * j + grp;
                atomicAdd(&g_n2[pair][1][b][n], sqb[j]);
            }
        }
    }
}

// stable descending argsort rank (count-based) + positives count
__global__ void k_rank(const float* __restrict__ gt) {
    __shared__ float row[NN];
    int batch = blockIdx.y;
    const float* gr = gt + batch * NN;
    for (int j = threadIdx.x; j < NN; j += 128) row[j] = gr[j];
    __syncthreads();

    int i = blockIdx.x * 128 + threadIdx.x;
    float xi = row[i];
    int cgt = 0, ceq = 0;
    for (int j = 0; j < NN; j += 4) {
        float4 v = *(const float4*)&row[j];
        cgt += (v.x > xi) + (v.y > xi) + (v.z > xi) + (v.w > xi);
        ceq += (v.x == xi && j     < i);
        ceq += (v.y == xi && j + 1 < i);
        ceq += (v.z == xi && j + 2 < i);
        ceq += (v.w == xi && j + 3 < i);
    }
    g_ord[batch][cgt + ceq] = i;

    int pos = (xi > 0.f) ? 1 : 0;
    #pragma unroll
    for (int o = 16; o; o >>= 1) pos += __shfl_down_sync(0xffffffffu, pos, o);
    __shared__ int ws[4];
    if ((threadIdx.x & 31) == 0) ws[threadIdx.x >> 5] = pos;
    __syncthreads();
    if (threadIdx.x == 0) atomicAdd(&g_cnt[batch], ws[0] + ws[1] + ws[2] + ws[3]);
}

// blocks [0,1024): masked cosine-embedding sum over sorted pairs (warp/position)
// block 1024: pearson over first 16 rows of flattened [B*N, C] (2 rows/warp)
__global__ void k_sepcos(const float* __restrict__ sep,
                         const float* __restrict__ px, const float* __restrict__ py) {
    int w = threadIdx.x >> 5, lane = threadIdx.x & 31;

    if (blockIdx.x == 1024) {
        #pragma unroll
        for (int rr = 0; rr < 2; rr++) {
            int rowi = w + rr * 8;      // 0..15
            const float4* xr = (const float4*)(px + rowi * CC);
            const float4* yr = (const float4*)(py + rowi * CC);
            float4 a = xr[lane], b = yr[lane];
            float sx  = a.x + a.y + a.z + a.w;
            float sy  = b.x + b.y + b.z + b.w;
            float sxx = a.x*a.x + a.y*a.y + a.z*a.z + a.w*a.w;
            float syy = b.x*b.x + b.y*b.y + b.z*b.z + b.w*b.w;
            float sxy = a.x*b.x + a.y*b.y + a.z*b.z + a.w*b.w;
            sx = wredf(sx); sy = wredf(sy); sxx = wredf(sxx);
            syy = wredf(syy); sxy = wredf(sxy);
            if (lane == 0) {
                double n = 128.0;
                double num = (double)sxy - (double)sx * (double)sy / n;
                double d2  = ((double)sxx - (double)sx * (double)sx / n) *
                             ((double)syy - (double)sy * (double)sy / n);
                double den = sqrt(d2);
                double r   = (den == 0.0) ? 0.0 : num / den;
                atomicAdd(&g_acc[0], 1.0 - r);
            }
        }
        return;
    }

    int p = blockIdx.x * 8 + w;
    int i0 = g_ord[0][p], i1 = g_ord[1][p];
    const float4* r0 = (const float4*)(sep + (size_t)i0 * CC);
    const float4* r1 = (const float4*)(sep + (size_t)NC + (size_t)i1 * CC);
    float4 a = r0[lane], b = r1[lane];
    float dot = a.x*b.x + a.y*b.y + a.z*b.z + a.w*b.w;
    float nx  = a.x*a.x + a.y*a.y + a.z*a.z + a.w*a.w;
    float ny  = b.x*b.x + b.y*b.y + b.z*b.z + b.w*b.w;
    dot = wredf(dot); nx = wredf(nx); ny = wredf(ny);

    __shared__ double part[8];
    if (lane == 0) {
        int s0 = g_cnt[0]; if (s0 == 0) s0 = NN;
        int s1 = g_cnt[1]; if (s1 == 0) s1 = NN;
        int index = min(s0, s1);
        float cs = dot / (fmaxf(sqrtf(nx), 1e-8f) * fmaxf(sqrtf(ny), 1e-8f));
        part[w] = (p < index) ? (double)(1.f - cs) : 0.0;
    }
    __syncthreads();
    if (threadIdx.x == 0) {
        double s = 0;
        #pragma unroll
        for (int k = 0; k < 8; k++) s += part[k];
        atomicAdd(&g_acc[1], s);
    }
}

// sum of squared normalized correlations over both pairs
__global__ void k_cost() {
    int idx  = blockIdx.x * 256 + threadIdx.x;
    int pair = idx >> 18;
    int rem  = idx & (BB*CC*CC - 1);
    int b    = rem >> 14;
    int cd   = rem & (CC*CC - 1);
    int c    = cd >> 7;
    int d    = cd & (CC - 1);
    float g  = g_G[pair][b][cd];
    float nx = fmaxf(sqrtf(g_n2[pair][0][b][c]), 1e-12f);
    float ns = fmaxf(sqrtf(g_n2[pair][1][b][d]), 1e-12f);
    float v  = g / (nx * ns);
    block_add((double)(v * v), &g_acc[2]);
}

__global__ void k_final(float* __restrict__ out) {
    double sim   = g_acc[0] / 16.0;
    double cost  = g_acc[2] / (double)(BB * CC * CC);
    double recon = (g_acc[3] + g_acc[4]) / (double)BNC;
    int s0 = g_cnt[0]; if (s0 == 0) s0 = NN;
    int s1 = g_cnt[1]; if (s1 == 0) s1 = NN;
    int index = min(s0, s1);
    double gnn = g_acc[1] / (double)index;
    out[0] = (float)(2.0 * sim + 1.0 * cost + 0.05 * recon + gnn);
}

// ---------------- launch ----------------------------------------------------
extern "C" void kernel_launch(void* const* d_in, const int* in_sizes, int n_in,
                              void* d_out, int out_size) {
    const float* hf_f = (const float*)d_in[0];
    const float* lf_f = (const float*)d_in[1];
    const float* hf_s = (const float*)d_in[2];
    const float* lf_s = (const float*)d_in[3];
    const float* hf_p = (const float*)d_in[4];
    const float* lf_p = (const float*)d_in[5];
    const float* r_hf = (const float*)d_in[6];
    const float* r_lf = (const float*)d_in[7];
    const float* sep  = (const float*)d_in[8];
    /* d_in[9] = noi_node: contributes exactly zero (diff_loss on batch-of-1) */
    const float* gt   = (const float*)d_in[10];
    float* out = (float*)d_out;

    k_init  <<<2080, 256>>>();
    k_prep  <<<dim3(NC/4/256, 4), 256>>>(hf_s, hf_p, lf_s, lf_p);
    k_rank  <<<dim3(64, 2), 128>>>(gt);
    k_gemm  <<<GEMM_CTAS + 2*RECON_CTAS_PER_PAIR, 256>>>(r_hf, hf_f, r_lf, lf_f);
    k_sepcos<<<1025, 256>>>(sep, hf_s, lf_s);
    k_cost  <<<2048, 256>>>();
    k_final <<<1, 1>>>(out);
}

// round 14
// speedup vs baseline: 1.1807x; 1.1807x over previous
#include <cuda_runtime.h>
#include <cuda_bf16.h>
#include <stdint.h>
#include <cstdint>
#include <math.h>

#define BB 16
#define NN 8192
#define CC 128
#define NC (NN*CC)          // 1048576
#define BNC (BB*NC)         // 16777216

// ---------------- scratch (device globals; no dynamic allocation) ----------
__device__ __nv_bfloat16 g_cbf[4][BNC]; // centered bf16: 0 hf_s, 1 hf_p, 2 lf_s, 3 lf_p
__device__ float  g_G[2][BB][CC*CC];    // Gram partials  (2 MB)
__device__ float  g_n2[2][2][BB][CC];   // [pair][0=x/1=s][b][c] centered sum-of-squares
__device__ int    g_ord[2][NN];         // descending-stable argsort of gt_rank rows 0,1
__device__ int    g_cnt[2];             // count(gt_rank[b] > 0)
__device__ double g_acc[8];             // 0 pearson, 1 sep, 2 cost, 3 recon_hf, 4 recon_lf

// ---------------- helpers ---------------------------------------------------
__device__ __forceinline__ float wredf(float v) {
    #pragma unroll
    for (int o = 16; o; o >>= 1) v += __shfl_down_sync(0xffffffffu, v, o);
    return v;
}

__device__ __forceinline__ void block_add(double v, double* target) {
    __shared__ double sd[8];
    #pragma unroll
    for (int o = 16; o; o >>= 1) v += __shfl_down_sync(0xffffffffu, v, o);
    int lane = threadIdx.x & 31, w = threadIdx.x >> 5;
    if (lane == 0) sd[w] = v;
    __syncthreads();
    if (threadIdx.x == 0) {
        double s = 0;
        int nw = blockDim.x >> 5;
        for (int i = 0; i < nw; i++) s += sd[i];
        atomicAdd(target, s);
    }
}

// PTX wrappers
__device__ __forceinline__ void ldsm_x4_t(uint32_t& r0, uint32_t& r1,
                                          uint32_t& r2, uint32_t& r3, uint32_t addr) {
    asm volatile("ldmatrix.sync.aligned.m8n8.x4.trans.shared.b16 {%0,%1,%2,%3}, [%4];"
        : "=r"(r0), "=r"(r1), "=r"(r2), "=r"(r3) : "r"(addr));
}

__device__ __forceinline__ void mma_bf16_16816(float& c0, float& c1, float& c2, float& c3,
                                               uint32_t a0, uint32_t a1, uint32_t a2, uint32_t a3,
                                               uint32_t b0, uint32_t b1) {
    asm volatile(
        "mma.sync.aligned.m16n8k16.row.col.f32.bf16.bf16.f32 "
        "{%0,%1,%2,%3}, {%4,%5,%6,%7}, {%8,%9}, {%0,%1,%2,%3};"
        : "+f"(c0), "+f"(c1), "+f"(c2), "+f"(c3)
        : "r"(a0), "r"(a1), "r"(a2), "r"(a3), "r"(b0), "r"(b1));
}

__device__ __forceinline__ void cpa16(uint32_t dst, const void* src) {
    asm volatile("cp.async.cg.shared.global [%0], [%1], 16;" :: "r"(dst), "l"(src));
}
__device__ __forceinline__ void cpa_commit() {
    asm volatile("cp.async.commit_group;" ::: "memory");
}
template<int N>
__device__ __forceinline__ void cpa_wait() {
    asm volatile("cp.async.wait_group %0;" :: "n"(N) : "memory");
}

// ---------------- kernels ---------------------------------------------------

__global__ void k_init() {
    int i = blockIdx.x * 256 + threadIdx.x;
    if (i < 2*BB*CC*CC) ((float*)g_G)[i] = 0.f;
    else {
        int j = i - 2*BB*CC*CC;
        if (j < 2*2*BB*CC) ((float*)g_n2)[j] = 0.f;
    }
    if (i < 8) g_acc[i] = 0.0;
    if (i < 2) g_cnt[i] = 0;
}

// fused batch-mean + centering + bf16 conversion (one read of each tensor)
__global__ void k_prep(const float* __restrict__ a, const float* __restrict__ b,
                       const float* __restrict__ c, const float* __restrict__ d) {
    int which = blockIdx.y;
    const float4* src;
    switch (which) {
        case 0:  src = (const float4*)a; break;
        case 1:  src = (const float4*)b; break;
        case 2:  src = (const float4*)c; break;
        default: src = (const float4*)d; break;
    }
    uint2* dst = (uint2*)g_cbf[which];
    int idx = blockIdx.x * 256 + threadIdx.x;       // float4 index 0..NC/4-1

    float4 v[BB];
    #pragma unroll
    for (int bb = 0; bb < BB; bb++) v[bb] = src[(size_t)bb * (NC/4) + idx];

    float4 m = make_float4(0.f, 0.f, 0.f, 0.f);
    #pragma unroll
    for (int bb = 0; bb < BB; bb++) {
        m.x += v[bb].x; m.y += v[bb].y; m.z += v[bb].z; m.w += v[bb].w;
    }
    m.x *= 0.0625f; m.y *= 0.0625f; m.z *= 0.0625f; m.w *= 0.0625f;

    #pragma unroll
    for (int bb = 0; bb < BB; bb++) {
        __nv_bfloat162 lo = __floats2bfloat162_rn(v[bb].x - m.x, v[bb].y - m.y);
        __nv_bfloat162 hi = __floats2bfloat162_rn(v[bb].z - m.z, v[bb].w - m.w);
        dst[(size_t)bb * (NC/4) + idx] = make_uint2(*(uint32_t*)&lo, *(uint32_t*)&hi);
    }
}

// ---- fused kernel: CTAs [0,256) = bf16 tensor-core split-K Gram;
//      CTAs [256,296) = reconstruction MSE with deep MLP (16 loads in flight)
//      so 40 CTAs can pull full DRAM bandwidth while gemm CTAs are
//      tensor/latency-bound.
__device__ __forceinline__ uint32_t swz(int row, int cbyte) {
    return (uint32_t)(row * 256 + (cbyte ^ ((row & 7) << 4)));
}

#define STAGE_BYTES 16384   // X 8KB + S 8KB
#define GEMM_CTAS 256
#define RECON_CTAS_PER_PAIR 20

__global__ __launch_bounds__(256, 2)
void k_gemm(const float* __restrict__ r_hf, const float* __restrict__ hf,
            const float* __restrict__ r_lf, const float* __restrict__ lf) {
    __shared__ __align__(16) unsigned char smem[3 * STAGE_BYTES];   // 48KB ring

    int t = threadIdx.x;

    // ================= recon branch (CTA-granular, MLP=16) =================
    if (blockIdx.x >= GEMM_CTAS) {
        int rid  = blockIdx.x - GEMM_CTAS;              // 0..39
        int pair = rid & 1;
        int slice = rid >> 1;                            // 0..19
        const float4* r = (const float4*)(pair ? r_lf : r_hf);
        const float4* o = (const float4*)(pair ? lf   : hf);
        const int nthr = RECON_CTAS_PER_PAIR * 256;      // 5120
        const int NC4  = BNC / 4;                        // 4194304 float4/pair
        int base = slice * 256 + t;
        float local = 0.f;
        for (int i = base; i < NC4; i += nthr * 8) {
            float4 ra[8], oa[8];
            #pragma unroll
            for (int u = 0; u < 8; u++) {
                int idx = i + u * nthr;
                if (idx < NC4) ra[u] = r[idx];
            }
            #pragma unroll
            for (int u = 0; u < 8; u++) {
                int idx = i + u * nthr;
                if (idx < NC4) oa[u] = o[idx];
            }
            #pragma unroll
            for (int u = 0; u < 8; u++) {
                int idx = i + u * nthr;
                if (idx < NC4) {
                    float dx = ra[u].x - oa[u].x, dy = ra[u].y - oa[u].y;
                    float dz = ra[u].z - oa[u].z, dw = ra[u].w - oa[u].w;
                    local += dx*dx + dy*dy + dz*dz + dw*dw;
                }
            }
        }
        block_add((double)local, &g_acc[3 + pair]);
        return;
    }

    // ================= gemm branch =================
    int cta  = blockIdx.x;
    int pair = cta >> 7;            // 0..1
    int b    = (cta >> 3) & 15;     // 0..15
    int kchunk = cta & 7;           // 0..7

    const __nv_bfloat16* Xb = g_cbf[pair ? 2 : 0] + (size_t)b * NC;
    const __nv_bfloat16* Sb = g_cbf[pair ? 3 : 1] + (size_t)b * NC;

    int lane = t & 31, warp = t >> 5;
    int wm = (warp >> 2) * 64;          // warp m-origin (c-dim of X): 0 or 64
    int wn = (warp & 3) * 32;           // warp n-origin (c-dim of S): 0..96

    uint32_t sbase = (uint32_t)__cvta_generic_to_shared(smem);

    // loader mapping: 256 threads x 32B per tensor per stage (2 x 16B chunks)
    int lrow = t >> 3;                  // 0..31
    int lc8  = t & 7;                   // chunk pair 0..7
    uint32_t ld0 = swz(lrow, lc8 * 32);
    uint32_t ld1 = swz(lrow, lc8 * 32 + 16);
    int lsrc = lrow * CC + lc8 * 16;    // bf16 element offset within stage

    // ldmatrix.x4.trans lane address pieces
    int a_r = ((lane >> 4) & 1) * 8 + (lane & 7);
    int a_c = ((lane >> 3) & 1) * 8;
    int b_r = ((lane >> 3) & 1) * 8 + (lane & 7);
    int b_c = ((lane >> 4) & 1) * 8;

    float acc[4][16];
    #pragma unroll
    for (int i = 0; i < 4; i++)
        #pragma unroll
        for (int j = 0; j < 16; j++) acc[i][j] = 0.f;

    float sqa[8] = {0.f,0.f,0.f,0.f,0.f,0.f,0.f,0.f}; // warps 0,4: X col sums (64 rows)
    float sqb[4] = {0.f,0.f,0.f,0.f};                  // warps 0..3: S col sums (32 rows)
    bool doA = ((warp & 3) == 0);
    bool doB = ((warp >> 2) == 0);

    int kbase = kchunk * 1024;          // 32 stages of 32 k-rows

    // prologue: issue stages 0..1
    #pragma unroll
    for (int st = 0; st < 2; st++) {
        uint32_t sb = sbase + st * STAGE_BYTES;
        int gsrc = (kbase + st * 32) * CC + lsrc;
        cpa16(sb + ld0,        Xb + gsrc);
        cpa16(sb + ld1,        Xb + gsrc + 8);
        cpa16(sb + 8192 + ld0, Sb + gsrc);
        cpa16(sb + 8192 + ld1, Sb + gsrc + 8);
        cpa_commit();
    }

    int slot = 0;   // ring slot of stage st
    for (int st = 0; st < 32; st++) {
        cpa_wait<1>();
        __syncthreads();

        // issue stage st+2 into the slot just freed
        int nslot = slot + 2; if (nslot >= 3) nslot -= 3;
        if (st + 2 < 32) {
            uint32_t sb = sbase + nslot * STAGE_BYTES;
            int gsrc = (kbase + (st + 2) * 32) * CC + lsrc;
            cpa16(sb + ld0,        Xb + gsrc);
            cpa16(sb + ld1,        Xb + gsrc + 8);
            cpa16(sb + 8192 + ld0, Sb + gsrc);
            cpa16(sb + 8192 + ld1, Sb + gsrc + 8);
        }
        cpa_commit();

        uint32_t sX = sbase + slot * STAGE_BYTES;
        uint32_t sS = sX + 8192;
        #pragma unroll
        for (int kk = 0; kk < 32; kk += 16) {
            uint32_t A0[4], A1[4], A2[4], A3[4], B0[4], B1[4];
            int ra = kk + a_r;
            ldsm_x4_t(A0[0], A0[1], A0[2], A0[3], sX + swz(ra, (wm      + a_c) * 2));
            ldsm_x4_t(A1[0], A1[1], A1[2], A1[3], sX + swz(ra, (wm + 16 + a_c) * 2));
            ldsm_x4_t(A2[0], A2[1], A2[2], A2[3], sX + swz(ra, (wm + 32 + a_c) * 2));
            ldsm_x4_t(A3[0], A3[1], A3[2], A3[3], sX + swz(ra, (wm + 48 + a_c) * 2));
            int rb = kk + b_r;
            ldsm_x4_t(B0[0], B0[1], B0[2], B0[3], sS + swz(rb, (wn      + b_c) * 2));
            ldsm_x4_t(B1[0], B1[1], B1[2], B1[3], sS + swz(rb, (wn + 16 + b_c) * 2));

            #pragma unroll
            for (int i = 0; i < 4; i++) {
                uint32_t* Ai = (i == 0) ? A0 : (i == 1) ? A1 : (i == 2) ? A2 : A3;
                mma_bf16_16816(acc[i][0],  acc[i][1],  acc[i][2],  acc[i][3],
                               Ai[0], Ai[1], Ai[2], Ai[3], B0[0], B0[1]);
                mma_bf16_16816(acc[i][4],  acc[i][5],  acc[i][6],  acc[i][7],
                               Ai[0], Ai[1], Ai[2], Ai[3], B0[2], B0[3]);
                mma_bf16_16816(acc[i][8],  acc[i][9],  acc[i][10], acc[i][11],
                               Ai[0], Ai[1], Ai[2], Ai[3], B1[0], B1[1]);
                mma_bf16_16816(acc[i][12], acc[i][13], acc[i][14], acc[i][15],
                               Ai[0], Ai[1], Ai[2], Ai[3], B1[2], B1[3]);
            }

            // fragment-derived sums of squares (each tile element counted once)
            if (doA) {
                #pragma unroll
                for (int i = 0; i < 4; i++) {
                    uint32_t* Ai = (i == 0) ? A0 : (i == 1) ? A1 : (i == 2) ? A2 : A3;
                    float2 f0 = __bfloat1622float2(*(__nv_bfloat162*)&Ai[0]);
                    float2 f1 = __bfloat1622float2(*(__nv_bfloat162*)&Ai[1]);
                    float2 f2 = __bfloat1622float2(*(__nv_bfloat162*)&Ai[2]);
                    float2 f3 = __bfloat1622float2(*(__nv_bfloat162*)&Ai[3]);
                    sqa[i*2+0] += f0.x*f0.x + f0.y*f0.y + f2.x*f2.x + f2.y*f2.y;
                    sqa[i*2+1] += f1.x*f1.x + f1.y*f1.y + f3.x*f3.x + f3.y*f3.y;
                }
            }
            if (doB) {
                float2 g0 = __bfloat1622float2(*(__nv_bfloat162*)&B0[0]);
                float2 g1 = __bfloat1622float2(*(__nv_bfloat162*)&B0[1]);
                float2 g2 = __bfloat1622float2(*(__nv_bfloat162*)&B0[2]);
                float2 g3 = __bfloat1622float2(*(__nv_bfloat162*)&B0[3]);
                float2 h0 = __bfloat1622float2(*(__nv_bfloat162*)&B1[0]);
                float2 h1 = __bfloat1622float2(*(__nv_bfloat162*)&B1[1]);
                float2 h2 = __bfloat1622float2(*(__nv_bfloat162*)&B1[2]);
                float2 h3 = __bfloat1622float2(*(__nv_bfloat162*)&B1[3]);
                sqb[0] += g0.x*g0.x + g0.y*g0.y + g1.x*g1.x + g1.y*g1.y;
                sqb[1] += g2.x*g2.x + g2.y*g2.y + g3.x*g3.x + g3.y*g3.y;
                sqb[2] += h0.x*h0.x + h0.y*h0.y + h1.x*h1.x + h1.y*h1.y;
                sqb[3] += h2.x*h2.x + h2.y*h2.y + h3.x*h3.x + h3.y*h3.y;
            }
        }
        __syncthreads();
        slot++; if (slot == 3) slot = 0;
    }

    // epilogue: merge split-K partials
    float* Gp = g_G[pair][b];
    int grp = lane >> 2, tg = lane & 3;
    #pragma unroll
    for (int i = 0; i < 4; i++) {
        #pragma unroll
        for (int j2 = 0; j2 < 4; j2++) {
            int m = wm + 16 * i + grp;
            int d = wn + 8 * j2 + tg * 2;
            atomicAdd(&Gp[m * CC + d],           acc[i][j2 * 4 + 0]);
            atomicAdd(&Gp[m * CC + d + 1],       acc[i][j2 * 4 + 1]);
            atomicAdd(&Gp[(m + 8) * CC + d],     acc[i][j2 * 4 + 2]);
            atomicAdd(&Gp[(m + 8) * CC + d + 1], acc[i][j2 * 4 + 3]);
        }
    }
    // n2 partials: xor-shuffle reduce over the 4 lanes sharing a column
    if (doA) {
        #pragma unroll
        for (int j = 0; j < 8; j++) {
            sqa[j] += __shfl_xor_sync(0xffffffffu, sqa[j], 1);
            sqa[j] += __shfl_xor_sync(0xffffffffu, sqa[j], 2);
        }
        if ((lane & 3) == 0) {
            #pragma unroll
            for (int j = 0; j < 8; j++) {
                int m = wm + 16 * (j >> 1) + 8 * (j & 1) + grp;
                atomicAdd(&g_n2[pair][0][b][m], sqa[j]);
            }
        }
    }
    if (doB) {
        #pragma unroll
        for (int j = 0; j < 4; j++) {
            sqb[j] += __shfl_xor_sync(0xffffffffu, sqb[j], 1);
            sqb[j] += __shfl_xor_sync(0xffffffffu, sqb[j], 2);
        }
        if ((lane & 3) == 0) {
            #pragma unroll
            for (int j = 0; j < 4; j++) {
                int n = wn + 8 * j + grp;
                atomicAdd(&g_n2[pair][1][b][n], sqb[j]);
            }
        }
    }
}

// stable descending argsort rank (count-based) + positives count
__global__ void k_rank(const float* __restrict__ gt) {
    __shared__ float row[NN];
    int batch = blockIdx.y;
    const float* gr = gt + batch * NN;
    for (int j = threadIdx.x; j < NN; j += 128) row[j] = gr[j];
    __syncthreads();

    int i = blockIdx.x * 128 + threadIdx.x;
    float xi = row[i];
    int cgt = 0, ceq = 0;
    for (int j = 0; j < NN; j += 4) {
        float4 v = *(const float4*)&row[j];
        cgt += (v.x > xi) + (v.y > xi) + (v.z > xi) + (v.w > xi);
        ceq += (v.x == xi && j     < i);
        ceq += (v.y == xi && j + 1 < i);
        ceq += (v.z == xi && j + 2 < i);
        ceq += (v.w == xi && j + 3 < i);
    }
    g_ord[batch][cgt + ceq] = i;

    int pos = (xi > 0.f) ? 1 : 0;
    #pragma unroll
    for (int o = 16; o; o >>= 1) pos += __shfl_down_sync(0xffffffffu, pos, o);
    __shared__ int ws[4];
    if ((threadIdx.x & 31) == 0) ws[threadIdx.x >> 5] = pos;
    __syncthreads();
    if (threadIdx.x == 0) atomicAdd(&g_cnt[batch], ws[0] + ws[1] + ws[2] + ws[3]);
}

// blocks [0,1024): masked cosine-embedding sum over sorted pairs (warp/position)
// block 1024: pearson over first 16 rows of flattened [B*N, C] (2 rows/warp)
__global__ void k_sepcos(const float* __restrict__ sep,
                         const float* __restrict__ px, const float* __restrict__ py) {
    int w = threadIdx.x >> 5, lane = threadIdx.x & 31;

    if (blockIdx.x == 1024) {
        #pragma unroll
        for (int rr = 0; rr < 2; rr++) {
            int rowi = w + rr * 8;      // 0..15
            const float4* xr = (const float4*)(px + rowi * CC);
            const float4* yr = (const float4*)(py + rowi * CC);
            float4 a = xr[lane], b = yr[lane];
            float sx  = a.x + a.y + a.z + a.w;
            float sy  = b.x + b.y + b.z + b.w;
            float sxx = a.x*a.x + a.y*a.y + a.z*a.z + a.w*a.w;
            float syy = b.x*b.x + b.y*b.y + b.z*b.z + b.w*b.w;
            float sxy = a.x*b.x + a.y*b.y + a.z*b.z + a.w*b.w;
            sx = wredf(sx); sy = wredf(sy); sxx = wredf(sxx);
            syy = wredf(syy); sxy = wredf(sxy);
            if (lane == 0) {
                double n = 128.0;
                double num = (double)sxy - (double)sx * (double)sy / n;
                double d2  = ((double)sxx - (double)sx * (double)sx / n) *
                             ((double)syy - (double)sy * (double)sy / n);
                double den = sqrt(d2);
                double r   = (den == 0.0) ? 0.0 : num / den;
                atomicAdd(&g_acc[0], 1.0 - r);
            }
        }
        return;
    }

    int p = blockIdx.x * 8 + w;
    int i0 = g_ord[0][p], i1 = g_ord[1][p];
    const float4* r0 = (const float4*)(sep + (size_t)i0 * CC);
    const float4* r1 = (const float4*)(sep + (size_t)NC + (size_t)i1 * CC);
    float4 a = r0[lane], b = r1[lane];
    float dot = a.x*b.x + a.y*b.y + a.z*b.z + a.w*b.w;
    float nx  = a.x*a.x + a.y*a.y + a.z*a.z + a.w*a.w;
    float ny  = b.x*b.x + b.y*b.y + b.z*b.z + b.w*b.w;
    dot = wredf(dot); nx = wredf(nx); ny = wredf(ny);

    __shared__ double part[8];
    if (lane == 0) {
        int s0 = g_cnt[0]; if (s0 == 0) s0 = NN;
        int s1 = g_cnt[1]; if (s1 == 0) s1 = NN;
        int index = min(s0, s1);
        float cs = dot / (fmaxf(sqrtf(nx), 1e-8f) * fmaxf(sqrtf(ny), 1e-8f));
        part[w] = (p < index) ? (double)(1.f - cs) : 0.0;
    }
    __syncthreads();
    if (threadIdx.x == 0) {
        double s = 0;
        #pragma unroll
        for (int k = 0; k < 8; k++) s += part[k];
        atomicAdd(&g_acc[1], s);
    }
}

// sum of squared normalized correlations over both pairs
__global__ void k_cost() {
    int idx  = blockIdx.x * 256 + threadIdx.x;
    int pair = idx >> 18;
    int rem  = idx & (BB*CC*CC - 1);
    int b    = rem >> 14;
    int cd   = rem & (CC*CC - 1);
    int c    = cd >> 7;
    int d    = cd & (CC - 1);
    float g  = g_G[pair][b][cd];
    float nx = fmaxf(sqrtf(g_n2[pair][0][b][c]), 1e-12f);
    float ns = fmaxf(sqrtf(g_n2[pair][1][b][d]), 1e-12f);
    float v  = g / (nx * ns);
    block_add((double)(v * v), &g_acc[2]);
}

__global__ void k_final(float* __restrict__ out) {
    double sim   = g_acc[0] / 16.0;
    double cost  = g_acc[2] / (double)(BB * CC * CC);
    double recon = (g_acc[3] + g_acc[4]) / (double)BNC;
    int s0 = g_cnt[0]; if (s0 == 0) s0 = NN;
    int s1 = g_cnt[1]; if (s1 == 0) s1 = NN;
    int index = min(s0, s1);
    double gnn = g_acc[1] / (double)index;
    out[0] = (float)(2.0 * sim + 1.0 * cost + 0.05 * recon + gnn);
}

// ---------------- launch ----------------------------------------------------
extern "C" void kernel_launch(void* const* d_in, const int* in_sizes, int n_in,
                              void* d_out, int out_size) {
    const float* hf_f = (const float*)d_in[0];
    const float* lf_f = (const float*)d_in[1];
    const float* hf_s = (const float*)d_in[2];
    const float* lf_s = (const float*)d_in[3];
    const float* hf_p = (const float*)d_in[4];
    const float* lf_p = (const float*)d_in[5];
    const float* r_hf = (const float*)d_in[6];
    const float* r_lf = (const float*)d_in[7];
    const float* sep  = (const float*)d_in[8];
    /* d_in[9] = noi_node: contributes exactly zero (diff_loss on batch-of-1) */
    const float* gt   = (const float*)d_in[10];
    float* out = (float*)d_out;

    k_init  <<<2080, 256>>>();
    k_prep  <<<dim3(NC/4/256, 4), 256>>>(hf_s, hf_p, lf_s, lf_p);
    k_rank  <<<dim3(64, 2), 128>>>(gt);
    k_gemm  <<<GEMM_CTAS + 2*RECON_CTAS_PER_PAIR, 256>>>(r_hf, hf_f, r_lf, lf_f);
    k_sepcos<<<1025, 256>>>(sep, hf_s, lf_s);
    k_cost  <<<2048, 256>>>();
    k_final <<<1, 1>>>(out);
}

// round 15
// speedup vs baseline: 1.4611x; 1.2375x over previous
#include <cuda_runtime.h>
#include <cuda_bf16.h>
#include <stdint.h>
#include <cstdint>
#include <math.h>

#define BB 16
#define NN 8192
#define CC 128
#define NC (NN*CC)          // 1048576
#define BNC (BB*NC)         // 16777216

// ---------------- scratch (device globals; no dynamic allocation) ----------
__device__ __nv_bfloat16 g_cbf[4][BNC]; // centered bf16: 0 hf_s, 1 hf_p, 2 lf_s, 3 lf_p
__device__ float  g_G[2][BB][CC*CC];    // Gram partials  (2 MB)
__device__ float  g_n2[2][2][BB][CC];   // [pair][0=x/1=s][b][c] centered sum-of-squares
__device__ int    g_ord[2][NN];         // descending-stable argsort of gt_rank rows 0,1
__device__ int    g_cnt[2];             // count(gt_rank[b] > 0)
__device__ double g_acc[8];             // 0 pearson, 1 sep, 2 cost, 3 recon_hf, 4 recon_lf

// ---------------- helpers ---------------------------------------------------
__device__ __forceinline__ float wredf(float v) {
    #pragma unroll
    for (int o = 16; o; o >>= 1) v += __shfl_down_sync(0xffffffffu, v, o);
    return v;
}

__device__ __forceinline__ void block_add(double v, double* target) {
    __shared__ double sd[8];
    #pragma unroll
    for (int o = 16; o; o >>= 1) v += __shfl_down_sync(0xffffffffu, v, o);
    int lane = threadIdx.x & 31, w = threadIdx.x >> 5;
    if (lane == 0) sd[w] = v;
    __syncthreads();
    if (threadIdx.x == 0) {
        double s = 0;
        int nw = blockDim.x >> 5;
        for (int i = 0; i < nw; i++) s += sd[i];
        atomicAdd(target, s);
    }
}

// PTX wrappers
__device__ __forceinline__ void ldsm_x4_t(uint32_t& r0, uint32_t& r1,
                                          uint32_t& r2, uint32_t& r3, uint32_t addr) {
    asm volatile("ldmatrix.sync.aligned.m8n8.x4.trans.shared.b16 {%0,%1,%2,%3}, [%4];"
        : "=r"(r0), "=r"(r1), "=r"(r2), "=r"(r3) : "r"(addr));
}

__device__ __forceinline__ void mma_bf16_16816(float& c0, float& c1, float& c2, float& c3,
                                               uint32_t a0, uint32_t a1, uint32_t a2, uint32_t a3,
                                               uint32_t b0, uint32_t b1) {
    asm volatile(
        "mma.sync.aligned.m16n8k16.row.col.f32.bf16.bf16.f32 "
        "{%0,%1,%2,%3}, {%4,%5,%6,%7}, {%8,%9}, {%0,%1,%2,%3};"
        : "+f"(c0), "+f"(c1), "+f"(c2), "+f"(c3)
        : "r"(a0), "r"(a1), "r"(a2), "r"(a3), "r"(b0), "r"(b1));
}

__device__ __forceinline__ void cpa16(uint32_t dst, const void* src) {
    asm volatile("cp.async.cg.shared.global [%0], [%1], 16;" :: "r"(dst), "l"(src));
}
__device__ __forceinline__ void cpa_commit() {
    asm volatile("cp.async.commit_group;" ::: "memory");
}
template<int N>
__device__ __forceinline__ void cpa_wait() {
    asm volatile("cp.async.wait_group %0;" :: "n"(N) : "memory");
}

// ---------------- kernels ---------------------------------------------------

// fused batch-mean + centering + bf16 conversion (one read of each tensor);
// the which==0 CTAs also zero the accumulators (k_init folded in — all
// consumers of g_G/g_n2/g_acc/g_cnt launch after this kernel).
__global__ void k_prep(const float* __restrict__ a, const float* __restrict__ b,
                       const float* __restrict__ c, const float* __restrict__ d) {
    int which = blockIdx.y;
    const float4* src;
    switch (which) {
        case 0:  src = (const float4*)a; break;
        case 1:  src = (const float4*)b; break;
        case 2:  src = (const float4*)c; break;
        default: src = (const float4*)d; break;
    }
    uint2* dst = (uint2*)g_cbf[which];
    int idx = blockIdx.x * 256 + threadIdx.x;       // float4 index 0..NC/4-1

    if (which == 0) {
        // NC/4 = 262144 threads zero 2*BB*CC*CC = 524288 floats of g_G
        ((float2*)g_G)[idx] = make_float2(0.f, 0.f);
        if (idx < 2*2*BB*CC) ((float*)g_n2)[idx] = 0.f;
        if (idx < 8) g_acc[idx] = 0.0;
        if (idx < 2) g_cnt[idx] = 0;
    }

    float4 v[BB];
    #pragma unroll
    for (int bb = 0; bb < BB; bb++) v[bb] = src[(size_t)bb * (NC/4) + idx];

    float4 m = make_float4(0.f, 0.f, 0.f, 0.f);
    #pragma unroll
    for (int bb = 0; bb < BB; bb++) {
        m.x += v[bb].x; m.y += v[bb].y; m.z += v[bb].z; m.w += v[bb].w;
    }
    m.x *= 0.0625f; m.y *= 0.0625f; m.z *= 0.0625f; m.w *= 0.0625f;

    #pragma unroll
    for (int bb = 0; bb < BB; bb++) {
        __nv_bfloat162 lo = __floats2bfloat162_rn(v[bb].x - m.x, v[bb].y - m.y);
        __nv_bfloat162 hi = __floats2bfloat162_rn(v[bb].z - m.z, v[bb].w - m.w);
        dst[(size_t)bb * (NC/4) + idx] = make_uint2(*(uint32_t*)&lo, *(uint32_t*)&hi);
    }
}

// ---- fused kernel: CTAs [0,256) = bf16 tensor-core split-K Gram;
//      CTAs [256,472) = reconstruction MSE (216 small CTAs, deep MLP).
//      First wave = 256 gemm + 40 recon; as gemm CTAs drain, the scheduler
//      backfills freed slots with further recon CTAs -> DRAM stays busy.
__device__ __forceinline__ uint32_t swz(int row, int cbyte) {
    return (uint32_t)(row * 256 + (cbyte ^ ((row & 7) << 4)));
}

#define STAGE_BYTES 16384   // X 8KB + S 8KB
#define GEMM_CTAS 256
#define RECON_CTAS_PER_PAIR 108

__global__ __launch_bounds__(256, 2)
void k_gemm(const float* __restrict__ r_hf, const float* __restrict__ hf,
            const float* __restrict__ r_lf, const float* __restrict__ lf) {
    __shared__ __align__(16) unsigned char smem[3 * STAGE_BYTES];   // 48KB ring

    int t = threadIdx.x;

    // ================= recon branch (backfill CTAs, MLP=16) =================
    if (blockIdx.x >= GEMM_CTAS) {
        int rid  = blockIdx.x - GEMM_CTAS;               // 0..215
        int pair = rid & 1;
        int slice = rid >> 1;                            // 0..107
        const float4* r = (const float4*)(pair ? r_lf : r_hf);
        const float4* o = (const float4*)(pair ? lf   : hf);
        const int nthr = RECON_CTAS_PER_PAIR * 256;      // 27648
        const int NC4  = BNC / 4;                        // 4194304 float4/pair
        int base = slice * 256 + t;
        float local = 0.f;
        for (int i = base; i < NC4; i += nthr * 8) {
            float4 ra[8], oa[8];
            #pragma unroll
            for (int u = 0; u < 8; u++) {
                int idx = i + u * nthr;
                if (idx < NC4) ra[u] = r[idx];
            }
            #pragma unroll
            for (int u = 0; u < 8; u++) {
                int idx = i + u * nthr;
                if (idx < NC4) oa[u] = o[idx];
            }
            #pragma unroll
            for (int u = 0; u < 8; u++) {
                int idx = i + u * nthr;
                if (idx < NC4) {
                    float dx = ra[u].x - oa[u].x, dy = ra[u].y - oa[u].y;
                    float dz = ra[u].z - oa[u].z, dw = ra[u].w - oa[u].w;
                    local += dx*dx + dy*dy + dz*dz + dw*dw;
                }
            }
        }
        block_add((double)local, &g_acc[3 + pair]);
        return;
    }

    // ================= gemm branch =================
    int cta  = blockIdx.x;
    int pair = cta >> 7;            // 0..1
    int b    = (cta >> 3) & 15;     // 0..15
    int kchunk = cta & 7;           // 0..7

    const __nv_bfloat16* Xb = g_cbf[pair ? 2 : 0] + (size_t)b * NC;
    const __nv_bfloat16* Sb = g_cbf[pair ? 3 : 1] + (size_t)b * NC;

    int lane = t & 31, warp = t >> 5;
    int wm = (warp >> 2) * 64;          // warp m-origin (c-dim of X): 0 or 64
    int wn = (warp & 3) * 32;           // warp n-origin (c-dim of S): 0..96

    uint32_t sbase = (uint32_t)__cvta_generic_to_shared(smem);

    // loader mapping: 256 threads x 32B per tensor per stage (2 x 16B chunks)
    int lrow = t >> 3;                  // 0..31
    int lc8  = t & 7;                   // chunk pair 0..7
    uint32_t ld0 = swz(lrow, lc8 * 32);
    uint32_t ld1 = swz(lrow, lc8 * 32 + 16);
    int lsrc = lrow * CC + lc8 * 16;    // bf16 element offset within stage

    // ldmatrix.x4.trans lane address pieces
    int a_r = ((lane >> 4) & 1) * 8 + (lane & 7);
    int a_c = ((lane >> 3) & 1) * 8;
    int b_r = ((lane >> 3) & 1) * 8 + (lane & 7);
    int b_c = ((lane >> 4) & 1) * 8;

    float acc[4][16];
    #pragma unroll
    for (int i = 0; i < 4; i++)
        #pragma unroll
        for (int j = 0; j < 16; j++) acc[i][j] = 0.f;

    float sqa[8] = {0.f,0.f,0.f,0.f,0.f,0.f,0.f,0.f}; // warps 0,4: X col sums (64 rows)
    float sqb[4] = {0.f,0.f,0.f,0.f};                  // warps 0..3: S col sums (32 rows)
    bool doA = ((warp & 3) == 0);
    bool doB = ((warp >> 2) == 0);

    int kbase = kchunk * 1024;          // 32 stages of 32 k-rows

    // prologue: issue stages 0..1
    #pragma unroll
    for (int st = 0; st < 2; st++) {
        uint32_t sb = sbase + st * STAGE_BYTES;
        int gsrc = (kbase + st * 32) * CC + lsrc;
        cpa16(sb + ld0,        Xb + gsrc);
        cpa16(sb + ld1,        Xb + gsrc + 8);
        cpa16(sb + 8192 + ld0, Sb + gsrc);
        cpa16(sb + 8192 + ld1, Sb + gsrc + 8);
        cpa_commit();
    }

    int slot = 0;   // ring slot of stage st
    for (int st = 0; st < 32; st++) {
        cpa_wait<1>();
        __syncthreads();

        // issue stage st+2 into the slot just freed
        int nslot = slot + 2; if (nslot >= 3) nslot -= 3;
        if (st + 2 < 32) {
            uint32_t sb = sbase + nslot * STAGE_BYTES;
            int gsrc = (kbase + (st + 2) * 32) * CC + lsrc;
            cpa16(sb + ld0,        Xb + gsrc);
            cpa16(sb + ld1,        Xb + gsrc + 8);
            cpa16(sb + 8192 + ld0, Sb + gsrc);
            cpa16(sb + 8192 + ld1, Sb + gsrc + 8);
        }
        cpa_commit();

        uint32_t sX = sbase + slot * STAGE_BYTES;
        uint32_t sS = sX + 8192;
        #pragma unroll
        for (int kk = 0; kk < 32; kk += 16) {
            uint32_t A0[4], A1[4], A2[4], A3[4], B0[4], B1[4];
            int ra = kk + a_r;
            ldsm_x4_t(A0[0], A0[1], A0[2], A0[3], sX + swz(ra, (wm      + a_c) * 2));
            ldsm_x4_t(A1[0], A1[1], A1[2], A1[3], sX + swz(ra, (wm + 16 + a_c) * 2));
            ldsm_x4_t(A2[0], A2[1], A2[2], A2[3], sX + swz(ra, (wm + 32 + a_c) * 2));
            ldsm_x4_t(A3[0], A3[1], A3[2], A3[3], sX + swz(ra, (wm + 48 + a_c) * 2));
            int rb = kk + b_r;
            ldsm_x4_t(B0[0], B0[1], B0[2], B0[3], sS + swz(rb, (wn      + b_c) * 2));
            ldsm_x4_t(B1[0], B1[1], B1[2], B1[3], sS + swz(rb, (wn + 16 + b_c) * 2));

            #pragma unroll
            for (int i = 0; i < 4; i++) {
                uint32_t* Ai = (i == 0) ? A0 : (i == 1) ? A1 : (i == 2) ? A2 : A3;
                mma_bf16_16816(acc[i][0],  acc[i][1],  acc[i][2],  acc[i][3],
                               Ai[0], Ai[1], Ai[2], Ai[3], B0[0], B0[1]);
                mma_bf16_16816(acc[i][4],  acc[i][5],  acc[i][6],  acc[i][7],
                               Ai[0], Ai[1], Ai[2], Ai[3], B0[2], B0[3]);
                mma_bf16_16816(acc[i][8],  acc[i][9],  acc[i][10], acc[i][11],
                               Ai[0], Ai[1], Ai[2], Ai[3], B1[0], B1[1]);
                mma_bf16_16816(acc[i][12], acc[i][13], acc[i][14], acc[i][15],
                               Ai[0], Ai[1], Ai[2], Ai[3], B1[2], B1[3]);
            }

            // fragment-derived sums of squares (each tile element counted once)
            if (doA) {
                #pragma unroll
                for (int i = 0; i < 4; i++) {
                    uint32_t* Ai = (i == 0) ? A0 : (i == 1) ? A1 : (i == 2) ? A2 : A3;
                    float2 f0 = __bfloat1622float2(*(__nv_bfloat162*)&Ai[0]);
                    float2 f1 = __bfloat1622float2(*(__nv_bfloat162*)&Ai[1]);
                    float2 f2 = __bfloat1622float2(*(__nv_bfloat162*)&Ai[2]);
                    float2 f3 = __bfloat1622float2(*(__nv_bfloat162*)&Ai[3]);
                    sqa[i*2+0] += f0.x*f0.x + f0.y*f0.y + f2.x*f2.x + f2.y*f2.y;
                    sqa[i*2+1] += f1.x*f1.x + f1.y*f1.y + f3.x*f3.x + f3.y*f3.y;
                }
            }
            if (doB) {
                float2 g0 = __bfloat1622float2(*(__nv_bfloat162*)&B0[0]);
                float2 g1 = __bfloat1622float2(*(__nv_bfloat162*)&B0[1]);
                float2 g2 = __bfloat1622float2(*(__nv_bfloat162*)&B0[2]);
                float2 g3 = __bfloat1622float2(*(__nv_bfloat162*)&B0[3]);
                float2 h0 = __bfloat1622float2(*(__nv_bfloat162*)&B1[0]);
                float2 h1 = __bfloat1622float2(*(__nv_bfloat162*)&B1[1]);
                float2 h2 = __bfloat1622float2(*(__nv_bfloat162*)&B1[2]);
                float2 h3 = __bfloat1622float2(*(__nv_bfloat162*)&B1[3]);
                sqb[0] += g0.x*g0.x + g0.y*g0.y + g1.x*g1.x + g1.y*g1.y;
                sqb[1] += g2.x*g2.x + g2.y*g2.y + g3.x*g3.x + g3.y*g3.y;
                sqb[2] += h0.x*h0.x + h0.y*h0.y + h1.x*h1.x + h1.y*h1.y;
                sqb[3] += h2.x*h2.x + h2.y*h2.y + h3.x*h3.x + h3.y*h3.y;
            }
        }
        __syncthreads();
        slot++; if (slot == 3) slot = 0;
    }

    // epilogue: merge split-K partials
    float* Gp = g_G[pair][b];
    int grp = lane >> 2, tg = lane & 3;
    #pragma unroll
    for (int i = 0; i < 4; i++) {
        #pragma unroll
        for (int j2 = 0; j2 < 4; j2++) {
            int m = wm + 16 * i + grp;
            int d = wn + 8 * j2 + tg * 2;
            atomicAdd(&Gp[m * CC + d],           acc[i][j2 * 4 + 0]);
            atomicAdd(&Gp[m * CC + d + 1],       acc[i][j2 * 4 + 1]);
            atomicAdd(&Gp[(m + 8) * CC + d],     acc[i][j2 * 4 + 2]);
            atomicAdd(&Gp[(m + 8) * CC + d + 1], acc[i][j2 * 4 + 3]);
        }
    }
    // n2 partials: xor-shuffle reduce over the 4 lanes sharing a column
    if (doA) {
        #pragma unroll
        for (int j = 0; j < 8; j++) {
            sqa[j] += __shfl_xor_sync(0xffffffffu, sqa[j], 1);
            sqa[j] += __shfl_xor_sync(0xffffffffu, sqa[j], 2);
        }
        if ((lane & 3) == 0) {
            #pragma unroll
            for (int j = 0; j < 8; j++) {
                int m = wm + 16 * (j >> 1) + 8 * (j & 1) + grp;
                atomicAdd(&g_n2[pair][0][b][m], sqa[j]);
            }
        }
    }
    if (doB) {
        #pragma unroll
        for (int j = 0; j < 4; j++) {
            sqb[j] += __shfl_xor_sync(0xffffffffu, sqb[j], 1);
            sqb[j] += __shfl_xor_sync(0xffffffffu, sqb[j], 2);
        }
        if ((lane & 3) == 0) {
            #pragma unroll
            for (int j = 0; j < 4; j++) {
                int n = wn + 8 * j + grp;
                atomicAdd(&g_n2[pair][1][b][n], sqb[j]);
            }
        }
    }
}

// stable descending argsort rank (count-based) + positives count
__global__ void k_rank(const float* __restrict__ gt) {
    __shared__ float row[NN];
    int batch = blockIdx.y;
    const float* gr = gt + batch * NN;
    for (int j = threadIdx.x; j < NN; j += 128) row[j] = gr[j];
    __syncthreads();

    int i = blockIdx.x * 128 + threadIdx.x;
    float xi = row[i];
    int cgt = 0, ceq = 0;
    for (int j = 0; j < NN; j += 4) {
        float4 v = *(const float4*)&row[j];
        cgt += (v.x > xi) + (v.y > xi) + (v.z > xi) + (v.w > xi);
        ceq += (v.x == xi && j     < i);
        ceq += (v.y == xi && j + 1 < i);
        ceq += (v.z == xi && j + 2 < i);
        ceq += (v.w == xi && j + 3 < i);
    }
    g_ord[batch][cgt + ceq] = i;

    int pos = (xi > 0.f) ? 1 : 0;
    #pragma unroll
    for (int o = 16; o; o >>= 1) pos += __shfl_down_sync(0xffffffffu, pos, o);
    __shared__ int ws[4];
    if ((threadIdx.x & 31) == 0) ws[threadIdx.x >> 5] = pos;
    __syncthreads();
    if (threadIdx.x == 0) atomicAdd(&g_cnt[batch], ws[0] + ws[1] + ws[2] + ws[3]);
}

// blocks [0,1024): masked cosine-embedding sum over sorted pairs (warp/position)
// block 1024: pearson over first 16 rows of flattened [B*N, C] (2 rows/warp)
__global__ void k_sepcos(const float* __restrict__ sep,
                         const float* __restrict__ px, const float* __restrict__ py) {
    int w = threadIdx.x >> 5, lane = threadIdx.x & 31;

    if (blockIdx.x == 1024) {
        #pragma unroll
        for (int rr = 0; rr < 2; rr++) {
            int rowi = w + rr * 8;      // 0..15
            const float4* xr = (const float4*)(px + rowi * CC);
            const float4* yr = (const float4*)(py + rowi * CC);
            float4 a = xr[lane], b = yr[lane];
            float sx  = a.x + a.y + a.z + a.w;
            float sy  = b.x + b.y + b.z + b.w;
            float sxx = a.x*a.x + a.y*a.y + a.z*a.z + a.w*a.w;
            float syy = b.x*b.x + b.y*b.y + b.z*b.z + b.w*b.w;
            float sxy = a.x*b.x + a.y*b.y + a.z*b.z + a.w*b.w;
            sx = wredf(sx); sy = wredf(sy); sxx = wredf(sxx);
            syy = wredf(syy); sxy = wredf(sxy);
            if (lane == 0) {
                double n = 128.0;
                double num = (double)sxy - (double)sx * (double)sy / n;
                double d2  = ((double)sxx - (double)sx * (double)sx / n) *
                             ((double)syy - (double)sy * (double)sy / n);
                double den = sqrt(d2);
                double r   = (den == 0.0) ? 0.0 : num / den;
                atomicAdd(&g_acc[0], 1.0 - r);
            }
        }
        return;
    }

    int p = blockIdx.x * 8 + w;
    int i0 = g_ord[0][p], i1 = g_ord[1][p];
    const float4* r0 = (const float4*)(sep + (size_t)i0 * CC);
    const float4* r1 = (const float4*)(sep + (size_t)NC + (size_t)i1 * CC);
    float4 a = r0[lane], b = r1[lane];
    float dot = a.x*b.x + a.y*b.y + a.z*b.z + a.w*b.w;
    float nx  = a.x*a.x + a.y*a.y + a.z*a.z + a.w*a.w;
    float ny  = b.x*b.x + b.y*b.y + b.z*b.z + b.w*b.w;
    dot = wredf(dot); nx = wredf(nx); ny = wredf(ny);

    __shared__ double part[8];
    if (lane == 0) {
        int s0 = g_cnt[0]; if (s0 == 0) s0 = NN;
        int s1 = g_cnt[1]; if (s1 == 0) s1 = NN;
        int index = min(s0, s1);
        float cs = dot / (fmaxf(sqrtf(nx), 1e-8f) * fmaxf(sqrtf(ny), 1e-8f));
        part[w] = (p < index) ? (double)(1.f - cs) : 0.0;
    }
    __syncthreads();
    if (threadIdx.x == 0) {
        double s = 0;
        #pragma unroll
        for (int k = 0; k < 8; k++) s += part[k];
        atomicAdd(&g_acc[1], s);
    }
}

// sum of squared normalized correlations over both pairs
__global__ void k_cost() {
    int idx  = blockIdx.x * 256 + threadIdx.x;
    int pair = idx >> 18;
    int rem  = idx & (BB*CC*CC - 1);
    int b    = rem >> 14;
    int cd   = rem & (CC*CC - 1);
    int c    = cd >> 7;
    int d    = cd & (CC - 1);
    float g  = g_G[pair][b][cd];
    float nx = fmaxf(sqrtf(g_n2[pair][0][b][c]), 1e-12f);
    float ns = fmaxf(sqrtf(g_n2[pair][1][b][d]), 1e-12f);
    float v  = g / (nx * ns);
    block_add((double)(v * v), &g_acc[2]);
}

__global__ void k_final(float* __restrict__ out) {
    double sim   = g_acc[0] / 16.0;
    double cost  = g_acc[2] / (double)(BB * CC * CC);
    double recon = (g_acc[3] + g_acc[4]) / (double)BNC;
    int s0 = g_cnt[0]; if (s0 == 0) s0 = NN;
    int s1 = g_cnt[1]; if (s1 == 0) s1 = NN;
    int index = min(s0, s1);
    double gnn = g_acc[1] / (double)index;
    out[0] = (float)(2.0 * sim + 1.0 * cost + 0.05 * recon + gnn);
}

// ---------------- launch ----------------------------------------------------
extern "C" void kernel_launch(void* const* d_in, const int* in_sizes, int n_in,
                              void* d_out, int out_size) {
    const float* hf_f = (const float*)d_in[0];
    const float* lf_f = (const float*)d_in[1];
    const float* hf_s = (const float*)d_in[2];
    const float* lf_s = (const float*)d_in[3];
    const float* hf_p = (const float*)d_in[4];
    const float* lf_p = (const float*)d_in[5];
    const float* r_hf = (const float*)d_in[6];
    const float* r_lf = (const float*)d_in[7];
    const float* sep  = (const float*)d_in[8];
    /* d_in[9] = noi_node: contributes exactly zero (diff_loss on batch-of-1) */
    const float* gt   = (const float*)d_in[10];
    float* out = (float*)d_out;

    k_prep  <<<dim3(NC/4/256, 4), 256>>>(hf_s, hf_p, lf_s, lf_p);
    k_rank  <<<dim3(64, 2), 128>>>(gt);
    k_gemm  <<<GEMM_CTAS + 2*RECON_CTAS_PER_PAIR, 256>>>(r_hf, hf_f, r_lf, lf_f);
    k_sepcos<<<1025, 256>>>(sep, hf_s, lf_s);
    k_cost  <<<2048, 256>>>();
    k_final <<<1, 1>>>(out);
}